// round 16
// baseline (speedup 1.0000x reference)
#include <cuda_runtime.h>
#include <cuda_fp16.h>
#include <cstdint>

#define DEVINL static __device__ __forceinline__

// ---------------- problem dims ----------------
#define B_SZ   8192
#define KTOT   2048           // IN + H fused K
#define NOUT   4096           // 4 gates x 1024
#define NTHREADS 512
#define NKT    (KTOT / 16)    // 128 kt16 steps

// scratch (device globals: allocation-free rule), fp16 fragment-order
// A: [mb64][kt128][mtglob8][lane32] uint4  (unchanged layout)
__device__ uint4 g_A[(size_t)B_SZ * KTOT / 8];          // 32 MB
// B: [nb16][kt128][w_n4][jp4][lane32] uint4  (pair-of-j packed for LDG.128)
__device__ uint4 g_B[(size_t)NOUT * KTOT / 8];          // 16 MB

// ---------------- helpers ----------------
DEVINL void mma16(float* d, const uint4& a, uint32_t b0, uint32_t b1){
  asm volatile(
    "mma.sync.aligned.m16n8k16.row.col.f32.f16.f16.f32 "
    "{%0,%1,%2,%3}, {%4,%5,%6,%7}, {%8,%9}, {%0,%1,%2,%3};"
    : "+f"(d[0]), "+f"(d[1]), "+f"(d[2]), "+f"(d[3])
    : "r"(a.x), "r"(a.y), "r"(a.z), "r"(a.w), "r"(b0), "r"(b1));
}
DEVINL float sigmoidf_(float x){ return 1.f / (1.f + __expf(-x)); }
DEVINL uint32_t pack2(float lo, float hi){
  __half2 v = __floats2half2_rn(lo, hi);
  return *reinterpret_cast<uint32_t*>(&v);
}

// ---------------- merged prep (A and B in ONE launch) ----------------
// A half (blocks [0, 8192)): m16n8k16 A-fragment order (as before)
//   idx = ((mb*128 + kt16)*8 + mtglob)*32 + lane
//   r = mb*128 + mtglob*16 + lane/4,  k = kt16*16 + (lane%4)*2,  A = [x | h]
// B half (blocks [8192, 12288)): uint4 = j-pair of B fragments
//   idx = (((nb*128 + kt)*4 + w_n)*4 + jp)*32 + lane
//   for s in {0,1}: j = 2*jp+s, nt = w_n*8+j, g = nt&3, cb = nt>>2
//   n = g*1024 + nb*64 + cb*8 + lane/4, k0 = kt*16 + (lane%4)*2, W = [Wx ; Wh]
//   v = { s0:pack2(W[k][n],W[k+1][n]), s0:pack2(W[k+8][n],W[k+9][n]),
//         s1:..., s1:... }
__global__ void prep_AB(const float* __restrict__ x, const float* __restrict__ h,
                        const float* __restrict__ Wx, const float* __restrict__ Wh){
  if (blockIdx.x < 8192){
    size_t idx = (size_t)blockIdx.x * 256 + threadIdx.x;   // [0, 2097152)
    int lane = (int)(idx & 31);
    int mt   = (int)((idx >> 5) & 7);
    int kt   = (int)((idx >> 8) & 127);
    int mb   = (int)(idx >> 15);
    int r = mb * 128 + mt * 16 + (lane >> 2);
    int k = kt * 16 + (lane & 3) * 2;
    const float* src = (k < 1024) ? x : h;
    int ko = k & 1023;
    const float* p0 = src + (size_t)r * 1024 + ko;
    const float* p1 = src + (size_t)(r + 8) * 1024 + ko;
    uint4 v;
    v.x = pack2(p0[0], p0[1]);
    v.y = pack2(p1[0], p1[1]);
    v.z = pack2(p0[8], p0[9]);
    v.w = pack2(p1[8], p1[9]);
    g_A[idx] = v;
  } else {
    size_t idx = (size_t)(blockIdx.x - 8192) * 256 + threadIdx.x;   // [0, 1048576)
    int lane = (int)(idx & 31);
    int jp   = (int)((idx >> 5) & 3);
    int wn   = (int)((idx >> 7) & 3);
    int kt   = (int)((idx >> 9) & 127);
    int nb   = (int)(idx >> 16);
    int k0 = kt * 16 + (lane & 3) * 2;
    const float* W = (k0 < 1024) ? Wx : Wh;
    int k = k0 & 1023;
    uint4 v;
    uint32_t comp[4];
    #pragma unroll
    for (int s = 0; s < 2; ++s){
      int j  = 2 * jp + s;
      int nt = wn * 8 + j;
      int g  = nt & 3, cb = nt >> 2;
      int n  = g * 1024 + nb * 64 + cb * 8 + (lane >> 2);
      comp[2*s]   = pack2(W[(size_t)k       * 4096 + n], W[(size_t)(k + 1) * 4096 + n]);
      comp[2*s+1] = pack2(W[(size_t)(k + 8) * 4096 + n], W[(size_t)(k + 9) * 4096 + n]);
    }
    v.x = comp[0]; v.y = comp[1]; v.z = comp[2]; v.w = comp[3];
    g_B[idx] = v;
  }
}

// ---------------- main fused GEMM + LSTM: NO SMEM, direct LDG fragments ----------
// 512 threads = 16 warps as 4x4 grid; warp tile 32 rows x 64 permuted cols.
// Operands are L2-resident (48MB, DRAM was 5.7%); each warp streams its own
// pre-packed fragments gmem->regs with 1-kt double buffering. No cp.async,
// no smem, no per-stage barriers (only a drift-bounding sync every 16 kt to
// keep L1 dedup across the 4-warp sharing groups effective).
__global__ void __launch_bounds__(NTHREADS, 1)
lstm_main(const float* __restrict__ c,
          const float* __restrict__ bx, const float* __restrict__ bh,
          float* __restrict__ out)
{
  const int tid = threadIdx.x;
  const int w   = tid >> 5;
  const int T   = tid & 31;
  const int w_m = w >> 2;          // 0..3 (32 rows each)
  const int w_n = w & 3;           // 0..3 (8 nt tiles each)
  const int nb  = blockIdx.x;      // 16
  const int mb  = blockIdx.y;      // 64

  // fragment stream bases (per warp, contiguous per kt)
  const uint4* pA = g_A + (size_t)mb * 32768 + (w_m * 2) * 32 + T;   // + kt*256, mt*32
  const uint4* pB = g_B + (size_t)nb * 65536 + (w_n * 4) * 32 + T;   // + kt*512, jp*32

  float acc[2][8][4];
  #pragma unroll
  for (int a = 0; a < 2; ++a)
    #pragma unroll
    for (int b = 0; b < 8; ++b)
      #pragma unroll
      for (int q = 0; q < 4; ++q) acc[a][b][q] = 0.f;

  uint4 aB[2][2], bB[2][4];

  // prologue: kt 0
  #pragma unroll
  for (int mt = 0; mt < 2; ++mt) aB[0][mt] = pA[mt * 32];
  #pragma unroll
  for (int jp = 0; jp < 4; ++jp) bB[0][jp] = pB[jp * 32];

  #pragma unroll 2
  for (int kt = 0; kt < NKT; ++kt){
    const int cur = kt & 1, nxt = cur ^ 1;
    if (kt + 1 < NKT){
      const uint4* nA = pA + (size_t)(kt + 1) * 256;
      const uint4* nB = pB + (size_t)(kt + 1) * 512;
      #pragma unroll
      for (int mt = 0; mt < 2; ++mt) aB[nxt][mt] = nA[mt * 32];
      #pragma unroll
      for (int jp = 0; jp < 4; ++jp) bB[nxt][jp] = nB[jp * 32];
    }
    #pragma unroll
    for (int mt = 0; mt < 2; ++mt)
      #pragma unroll
      for (int jp = 0; jp < 4; ++jp){
        mma16(acc[mt][2 * jp],     aB[cur][mt], bB[cur][jp].x, bB[cur][jp].y);
        mma16(acc[mt][2 * jp + 1], aB[cur][mt], bB[cur][jp].z, bB[cur][jp].w);
      }
    if ((kt & 15) == 15 && kt + 1 < NKT)
      __syncthreads();   // bound warp drift so L1 keeps shared fragment lines
  }

  // -------- fused LSTM epilogue (register-local: gates g at acc[.][jc*4+g]) --------
  const size_t S = (size_t)B_SZ * 1024;

  float bias[2][4][2];
  #pragma unroll
  for (int jc = 0; jc < 2; ++jc){
    int col = nb * 64 + (w_n * 2 + jc) * 8 + (T & 3) * 2;
    #pragma unroll
    for (int g = 0; g < 4; ++g)
      #pragma unroll
      for (int cc = 0; cc < 2; ++cc)
        bias[jc][g][cc] = bx[g * 1024 + col + cc] + bh[g * 1024 + col + cc];
  }

  #pragma unroll
  for (int mt = 0; mt < 2; ++mt){
    #pragma unroll
    for (int jc = 0; jc < 2; ++jc){
      int col = nb * 64 + (w_n * 2 + jc) * 8 + (T & 3) * 2;
      #pragma unroll
      for (int rr = 0; rr < 2; ++rr){
        int row = mb * 128 + w_m * 32 + mt * 16 + (T >> 2) + rr * 8;
        size_t ro = (size_t)row * 1024 + col;
        float2 cin = *(const float2*)(c + ro);
        float2 o2, h2v, c2;
        #pragma unroll
        for (int cc = 0; cc < 2; ++cc){
          int q = rr * 2 + cc;
          // j = jc*4 + g  maps to acc[.][2*jp+s] with jp = jc*2 + g/2, s = g&1;
          // since j = jc*4+g directly indexes acc[.][j], use it as before:
          float vi = acc[mt][jc * 4 + 0][q] + bias[jc][0][cc];
          float vf = acc[mt][jc * 4 + 1][q] + bias[jc][1][cc];
          float vg = acc[mt][jc * 4 + 2][q] + bias[jc][2][cc];
          float vo = acc[mt][jc * 4 + 3][q] + bias[jc][3][cc];
          float ig = sigmoidf_(vi);
          float fg = sigmoidf_(vf);
          float gg = tanhf(vg);
          float og = sigmoidf_(vo);
          float cv = (cc == 0) ? cin.x : cin.y;
          float cn = fg * cv + ig * gg;
          float hn = og * tanhf(cn);
          if (cc == 0){ o2.x = og; h2v.x = hn; c2.x = cn; }
          else        { o2.y = og; h2v.y = hn; c2.y = cn; }
        }
        *(float2*)(out + ro)         = o2;    // output gate
        *(float2*)(out + S + ro)     = h2v;   // h_new
        *(float2*)(out + 2 * S + ro) = c2;    // c_new
      }
    }
  }
}

// ---------------- launch ----------------
extern "C" void kernel_launch(void* const* d_in, const int* in_sizes, int n_in,
                              void* d_out, int out_size)
{
  const float* x  = (const float*)d_in[0];
  const float* h  = (const float*)d_in[1];
  const float* c  = (const float*)d_in[2];
  const float* Wx = (const float*)d_in[3];
  const float* Wh = (const float*)d_in[4];
  const float* bx = (const float*)d_in[5];
  const float* bh = (const float*)d_in[6];
  float* out = (float*)d_out;

  prep_AB<<<12288, 256>>>(x, h, Wx, Wh);   // A-half (8192) + B-half (4096) in one launch
  lstm_main<<<dim3(16, 64), NTHREADS>>>(c, bx, bh, out);
}